// round 7
// baseline (speedup 1.0000x reference)
#include <cuda_runtime.h>
#include <cuda_fp16.h>
#include <math.h>

// GCN 4 layers, N=100000, E=3200000, hidden=32.
// R6: fp16 feature rows (half2[16] per node, 64B) to halve L2 gather traffic.
// fp32 accumulation + transforms; half only at rest.
// FIX vs R3: remainder gather loop is now warp-uniform (both 16-lane groups run
// the same iteration count; shfl always executed by all 32 lanes).

#define N_MAX 100000
#define E_MAX 3200000
#define FULLMASK 0xffffffffu

__device__ int   g_deg[N_MAX];
__device__ int   g_off[N_MAX + 1];
__device__ int   g_cur[N_MAX];
__device__ int   g_csr[E_MAX];
__device__ float g_dinv[N_MAX];
__device__ unsigned int g_A[N_MAX * 16];   // half2-packed feature rows
__device__ unsigned int g_B[N_MAX * 16];
__device__ float g_s[N_MAX];               // width-1 buffer, fp32
__device__ int   g_bsums[512];

// ---------------- graph build ----------------

__global__ void k_count(const int* __restrict__ ei, int E) {
    int i = blockIdx.x * blockDim.x + threadIdx.x;
    if (i < E) atomicAdd(&g_deg[ei[E + i]], 1);
}

__global__ void k_scanA(int n) {
    __shared__ int sh[512];
    int t = threadIdx.x;
    int i = blockIdx.x * 512 + t;
    int v = (i < n) ? g_deg[i] : 0;
    if (i < n) g_dinv[i] = rsqrtf((float)(v + 1));
    sh[t] = v;
    __syncthreads();
    #pragma unroll
    for (int d = 1; d < 512; d <<= 1) {
        int x = (t >= d) ? sh[t - d] : 0;
        __syncthreads();
        sh[t] += x;
        __syncthreads();
    }
    if (i < n) g_off[i] = sh[t] - v;
    if (t == 511) g_bsums[blockIdx.x] = sh[511];
}

__global__ void k_scanB(int nb) {
    __shared__ int sh[512];
    int t = threadIdx.x;
    int v = (t < nb) ? g_bsums[t] : 0;
    sh[t] = v;
    __syncthreads();
    #pragma unroll
    for (int d = 1; d < 512; d <<= 1) {
        int x = (t >= d) ? sh[t - d] : 0;
        __syncthreads();
        sh[t] += x;
        __syncthreads();
    }
    if (t < nb) g_bsums[t] = sh[t] - v;
}

__global__ void k_scanC(int n, int E) {
    int i = blockIdx.x * 512 + threadIdx.x;
    if (i < n) g_off[i] += g_bsums[blockIdx.x];
    if (blockIdx.x == 0 && threadIdx.x == 0) g_off[n] = E;
}

__global__ void k_fill(const int* __restrict__ ei, int E) {
    int t = blockIdx.x * blockDim.x + threadIdx.x;
    if (t >= E) return;
    int s = ei[t];
    int d = ei[E + t];
    int p = atomicAdd(&g_cur[d], 1);
    g_csr[g_off[d] + p] = s;
}

// ---------------- layers ----------------

__device__ __forceinline__ float2 ldrow(const unsigned int* __restrict__ g,
                                        int node, int p) {
    __half2 h = *(const __half2*)(g + node * 16 + p);
    return __half22float2(h);
}

// Layer 1: g1[v] pair p = dinv[v]*x[v]*(W_in[2p], W_in[2p+1]) packed half2.
__global__ void k_l1(const float* __restrict__ x, const float* __restrict__ Win,
                     unsigned int* __restrict__ gout, int n) {
    int t = blockIdx.x * blockDim.x + threadIdx.x;
    if (t >= n * 16) return;
    int v = t >> 4, p = t & 15;
    float s = x[v] * g_dinv[v];
    float2 w = ((const float2*)Win)[p];
    __half2 hv = __floats2half2_rn(s * w.x, s * w.y);
    gout[t] = *(unsigned int*)&hv;
}

// Warp gather: fp32 pair-sum of neighbor rows + self row.
// lane = 32 lanes; p = lane&15 selects feature pair; group = lane>>4.
// Two groups gather alternating neighbors; combined via shfl_xor(…,16).
// ALL __shfl_sync calls are executed by all 32 lanes (uniform trip counts).
__device__ __forceinline__ float2 gather_half(const unsigned int* __restrict__ gin,
                                              int u, int lane) {
    int p = lane & 15;
    int group = lane >> 4;
    int s0 = g_off[u], s1 = g_off[u + 1];
    float2 a0 = make_float2(0.f, 0.f);
    float2 a1 = make_float2(0.f, 0.f);
    int e = s0;
    for (; e + 32 <= s1; e += 32) {
        int idx = g_csr[e + lane];
        #pragma unroll
        for (int k = 0; k < 16; k += 2) {
            int i0 = __shfl_sync(FULLMASK, idx, 2 * k + group);
            int i1 = __shfl_sync(FULLMASK, idx, 2 * (k + 1) + group);
            float2 v0 = ldrow(gin, i0, p);
            float2 v1 = ldrow(gin, i1, p);
            a0.x += v0.x; a0.y += v0.y;
            a1.x += v1.x; a1.y += v1.y;
        }
    }
    int rem = s1 - e;            // 0..31, uniform across warp
    if (rem > 0) {
        int idx = (e + lane < s1) ? g_csr[e + lane] : 0;
        int iters = (rem + 1) >> 1;              // uniform ceil(rem/2)
        for (int kk = 0; kk < iters; kk++) {
            int k = 2 * kk + group;              // k <= 31 always
            int s = __shfl_sync(FULLMASK, idx, k);
            if (k < rem) {
                float2 v = ldrow(gin, s, p);
                a0.x += v.x; a0.y += v.y;
            }
        }
    }
    float2 acc = make_float2(a0.x + a1.x, a0.y + a1.y);
    acc.x += __shfl_xor_sync(FULLMASK, acc.x, 16);
    acc.y += __shfl_xor_sync(FULLMASK, acc.y, 16);
    float2 self = ldrow(gin, u, p);
    acc.x += self.x;
    acc.y += self.y;
    return acc;   // identical in both groups
}

// Aggregate + relu + fused 32x32 transform -> next half2 g buffer.
__global__ void k_agg_mid(const unsigned int* __restrict__ gin,
                          const float* __restrict__ b,
                          const float* __restrict__ W,
                          unsigned int* __restrict__ gout, int n) {
    __shared__ float2 Wsh[512];            // [k][q]: (W[k][2q], W[k][2q+1])
    int t = threadIdx.x;
    for (int i = t; i < 512; i += blockDim.x)
        Wsh[i] = ((const float2*)W)[i];
    __syncthreads();
    int gt = blockIdx.x * blockDim.x + t;
    int u = gt >> 5, lane = gt & 31;
    if (u >= n) return;
    int p = lane & 15;
    float dinv = g_dinv[u];
    float2 acc = gather_half(gin, u, lane);
    float2 bb = ((const float2*)b)[p];
    float2 h;  // activated pair (2p, 2p+1); same value in both groups
    h.x = fmaxf(fmaf(dinv, acc.x, bb.x), 0.f);
    h.y = fmaxf(fmaf(dinv, acc.y, bb.y), 0.f);
    float2 o = make_float2(0.f, 0.f);
    #pragma unroll
    for (int k = 0; k < 32; k++) {
        float hk = __shfl_sync(FULLMASK, (k & 1) ? h.y : h.x, k >> 1);
        float2 w = Wsh[k * 16 + p];
        o.x = fmaf(hk, w.x, o.x);
        o.y = fmaf(hk, w.y, o.y);
    }
    if (lane < 16) {
        __half2 hv = __floats2half2_rn(dinv * o.x, dinv * o.y);
        gout[u * 16 + p] = *(unsigned int*)&hv;
    }
}

// Aggregate + relu + fused scalar transform -> g_s (fp32).
__global__ void k_agg_last(const unsigned int* __restrict__ gin,
                           const float* __restrict__ b,
                           const float* __restrict__ Wout, int n) {
    int gt = blockIdx.x * blockDim.x + threadIdx.x;
    int u = gt >> 5, lane = gt & 31;
    if (u >= n) return;
    int p = lane & 15;
    float dinv = g_dinv[u];
    float2 acc = gather_half(gin, u, lane);
    float2 bb = ((const float2*)b)[p];
    float2 w = ((const float2*)Wout)[p];
    float val = fmaxf(fmaf(dinv, acc.x, bb.x), 0.f) * w.x
              + fmaxf(fmaf(dinv, acc.y, bb.y), 0.f) * w.y;
    #pragma unroll
    for (int o = 1; o < 16; o <<= 1) val += __shfl_xor_sync(FULLMASK, val, o);
    if (lane == 0) g_s[u] = dinv * val;
}

// Final width-1 aggregation + bias + sigmoid.
__global__ void k_agg_out(const float* __restrict__ bout,
                          float* __restrict__ out, int n) {
    int gt = blockIdx.x * blockDim.x + threadIdx.x;
    int u = gt >> 5, lane = gt & 31;
    if (u >= n) return;
    int s0 = g_off[u], s1 = g_off[u + 1];
    float acc = 0.f;
    for (int e = s0 + lane; e < s1; e += 32) acc += g_s[g_csr[e]];
    #pragma unroll
    for (int o = 16; o; o >>= 1) acc += __shfl_xor_sync(FULLMASK, acc, o);
    if (lane == 0) {
        float v = fmaf(g_dinv[u], acc + g_s[u], bout[0]);
        out[u] = 1.f / (1.f + expf(-v));
    }
}

// ---------------- launch ----------------

extern "C" void kernel_launch(void* const* d_in, const int* in_sizes, int n_in,
                              void* d_out, int out_size) {
    const float* x    = (const float*)d_in[0];
    const int*   ei   = (const int*)  d_in[1];
    const float* Win  = (const float*)d_in[2];
    const float* bin  = (const float*)d_in[3];
    const float* Wmid = (const float*)d_in[4];
    const float* bmid = (const float*)d_in[5];
    const float* Wout = (const float*)d_in[6];
    const float* bout = (const float*)d_in[7];
    float* out = (float*)d_out;

    int n = in_sizes[0];
    int E = in_sizes[1] / 2;
    if (n > N_MAX) n = N_MAX;
    if (E > E_MAX) E = E_MAX;

    void *pA = nullptr, *pB = nullptr, *pDeg = nullptr, *pCur = nullptr;
    cudaGetSymbolAddress(&pA, g_A);
    cudaGetSymbolAddress(&pB, g_B);
    cudaGetSymbolAddress(&pDeg, g_deg);
    cudaGetSymbolAddress(&pCur, g_cur);
    unsigned int* A = (unsigned int*)pA;
    unsigned int* B = (unsigned int*)pB;

    const int T = 256;
    int gE   = (E + T - 1) / T;
    int gw   = (n * 32 + T - 1) / T;     // warp-per-node grids
    int gp   = (n * 16 + T - 1) / T;     // pair-per-thread grid (l1)
    int nbScan = (n + 511) / 512;

    cudaMemsetAsync(pDeg, 0, n * sizeof(int), 0);
    cudaMemsetAsync(pCur, 0, n * sizeof(int), 0);

    k_count<<<gE, T>>>(ei, E);
    k_scanA<<<nbScan, 512>>>(n);
    k_scanB<<<1, 512>>>(nbScan);
    k_scanC<<<nbScan, 512>>>(n, E);
    k_fill <<<gE, T>>>(ei, E);

    k_l1      <<<gp, T>>>(x, Win, A, n);
    k_agg_mid <<<gw, T>>>(A, bin,  Wmid, B, n);   // layer 1 agg + layer 2 transform
    k_agg_mid <<<gw, T>>>(B, bmid, Wmid, A, n);   // layer 2 agg + layer 3 transform
    k_agg_last<<<gw, T>>>(A, bmid, Wout, n);      // layer 3 agg + layer 4 transform
    k_agg_out <<<gw, T>>>(bout, out, n);          // layer 4 agg + sigmoid
}

// round 12
// speedup vs baseline: 1.2457x; 1.2457x over previous
#include <cuda_runtime.h>
#include <cuda_fp16.h>
#include <math.h>

// GCN 4 layers, N=100000, E=3200000, hidden=32.
// R7: gather restructured: 16-thread group per node, thread = feature pair
// (half2). Edge indices read via uniform loads (no shfl chain); edge loop
// unrolled x8 with independent accumulators -> high MLP, no serial remainder.
// fp16 feature rows (64B/node), fp32 accumulation and transforms.

#define N_MAX 100000
#define E_MAX 3200000
#define FULLMASK 0xffffffffu

__device__ int   g_deg[N_MAX];
__device__ int   g_off[N_MAX + 1];
__device__ int   g_cur[N_MAX];
__device__ int   g_csr[E_MAX];
__device__ float g_dinv[N_MAX];
__device__ unsigned int g_A[N_MAX * 16];   // half2-packed feature rows
__device__ unsigned int g_B[N_MAX * 16];
__device__ float g_s[N_MAX];               // width-1 buffer, fp32
__device__ int   g_bsums[512];

// ---------------- graph build ----------------

__global__ void k_count(const int* __restrict__ ei, int E) {
    int i = blockIdx.x * blockDim.x + threadIdx.x;
    if (i < E) atomicAdd(&g_deg[ei[E + i]], 1);
}

__global__ void k_scanA(int n) {
    __shared__ int sh[512];
    int t = threadIdx.x;
    int i = blockIdx.x * 512 + t;
    int v = (i < n) ? g_deg[i] : 0;
    if (i < n) g_dinv[i] = rsqrtf((float)(v + 1));
    sh[t] = v;
    __syncthreads();
    #pragma unroll
    for (int d = 1; d < 512; d <<= 1) {
        int x = (t >= d) ? sh[t - d] : 0;
        __syncthreads();
        sh[t] += x;
        __syncthreads();
    }
    if (i < n) g_off[i] = sh[t] - v;
    if (t == 511) g_bsums[blockIdx.x] = sh[511];
}

__global__ void k_scanB(int nb) {
    __shared__ int sh[512];
    int t = threadIdx.x;
    int v = (t < nb) ? g_bsums[t] : 0;
    sh[t] = v;
    __syncthreads();
    #pragma unroll
    for (int d = 1; d < 512; d <<= 1) {
        int x = (t >= d) ? sh[t - d] : 0;
        __syncthreads();
        sh[t] += x;
        __syncthreads();
    }
    if (t < nb) g_bsums[t] = sh[t] - v;
}

__global__ void k_scanC(int n, int E) {
    int i = blockIdx.x * 512 + threadIdx.x;
    if (i < n) g_off[i] += g_bsums[blockIdx.x];
    if (blockIdx.x == 0 && threadIdx.x == 0) g_off[n] = E;
}

__global__ void k_fill(const int* __restrict__ ei, int E) {
    int t = blockIdx.x * blockDim.x + threadIdx.x;
    if (t >= E) return;
    int s = ei[t];
    int d = ei[E + t];
    int p = atomicAdd(&g_cur[d], 1);
    g_csr[g_off[d] + p] = s;
}

// ---------------- layers ----------------

__device__ __forceinline__ float2 ldrow(const unsigned int* __restrict__ g,
                                        int node, int p) {
    unsigned int raw = __ldg(g + node * 16 + p);
    __half2 h = *(__half2*)&raw;
    return __half22float2(h);
}

// Layer 1: g1[v] pair p = dinv[v]*x[v]*(W_in[2p], W_in[2p+1]) packed half2.
__global__ void k_l1(const float* __restrict__ x, const float* __restrict__ Win,
                     unsigned int* __restrict__ gout, int n) {
    int t = blockIdx.x * blockDim.x + threadIdx.x;
    if (t >= n * 16) return;
    int v = t >> 4, p = t & 15;
    float s = x[v] * g_dinv[v];
    float2 w = ((const float2*)Win)[p];
    __half2 hv = __floats2half2_rn(s * w.x, s * w.y);
    gout[t] = *(unsigned int*)&hv;
}

// Per-thread gather: sum of neighbor feature pairs + self. No shfl, no
// cross-lane dependency; unroll x8 with 4 accumulators for MLP.
__device__ __forceinline__ float2 gather16(const unsigned int* __restrict__ gin,
                                           int u, int p) {
    int s0 = g_off[u], s1 = g_off[u + 1];
    float2 a0 = ldrow(gin, u, p);   // self loop
    float2 a1 = make_float2(0.f, 0.f);
    float2 a2 = make_float2(0.f, 0.f);
    float2 a3 = make_float2(0.f, 0.f);
    int e = s0;
    for (; e + 8 <= s1; e += 8) {
        int i0 = __ldg(&g_csr[e + 0]);
        int i1 = __ldg(&g_csr[e + 1]);
        int i2 = __ldg(&g_csr[e + 2]);
        int i3 = __ldg(&g_csr[e + 3]);
        int i4 = __ldg(&g_csr[e + 4]);
        int i5 = __ldg(&g_csr[e + 5]);
        int i6 = __ldg(&g_csr[e + 6]);
        int i7 = __ldg(&g_csr[e + 7]);
        float2 v0 = ldrow(gin, i0, p);
        float2 v1 = ldrow(gin, i1, p);
        float2 v2 = ldrow(gin, i2, p);
        float2 v3 = ldrow(gin, i3, p);
        float2 v4 = ldrow(gin, i4, p);
        float2 v5 = ldrow(gin, i5, p);
        float2 v6 = ldrow(gin, i6, p);
        float2 v7 = ldrow(gin, i7, p);
        a0.x += v0.x; a0.y += v0.y;
        a1.x += v1.x; a1.y += v1.y;
        a2.x += v2.x; a2.y += v2.y;
        a3.x += v3.x; a3.y += v3.y;
        a0.x += v4.x; a0.y += v4.y;
        a1.x += v5.x; a1.y += v5.y;
        a2.x += v6.x; a2.y += v6.y;
        a3.x += v7.x; a3.y += v7.y;
    }
    for (; e < s1; e++) {
        float2 v = ldrow(gin, __ldg(&g_csr[e]), p);
        a0.x += v.x; a0.y += v.y;
    }
    return make_float2((a0.x + a1.x) + (a2.x + a3.x),
                       (a0.y + a1.y) + (a2.y + a3.y));
}

// Aggregate + relu + fused 32x32 transform -> next half2 g buffer.
// 16 threads per node; width-16 shfl to broadcast h across the group.
__global__ void k_agg_mid(const unsigned int* __restrict__ gin,
                          const float* __restrict__ b,
                          const float* __restrict__ W,
                          unsigned int* __restrict__ gout, int n) {
    __shared__ float2 Wsh[512];            // [k][q]: (W[k][2q], W[k][2q+1])
    int t = threadIdx.x;
    for (int i = t; i < 512; i += blockDim.x)
        Wsh[i] = ((const float2*)W)[i];
    __syncthreads();
    int gt = blockIdx.x * blockDim.x + t;
    int u = gt >> 4, p = gt & 15;
    if (u >= n) return;
    float dinv = g_dinv[u];
    float2 acc = gather16(gin, u, p);
    float2 bb = ((const float2*)b)[p];
    float2 h;
    h.x = fmaxf(fmaf(dinv, acc.x, bb.x), 0.f);
    h.y = fmaxf(fmaf(dinv, acc.y, bb.y), 0.f);
    float2 o = make_float2(0.f, 0.f);
    #pragma unroll
    for (int k = 0; k < 32; k++) {
        float hk = __shfl_sync(FULLMASK, (k & 1) ? h.y : h.x, k >> 1, 16);
        float2 w = Wsh[k * 16 + p];
        o.x = fmaf(hk, w.x, o.x);
        o.y = fmaf(hk, w.y, o.y);
    }
    __half2 hv = __floats2half2_rn(dinv * o.x, dinv * o.y);
    gout[u * 16 + p] = *(unsigned int*)&hv;
}

// Aggregate + relu + fused scalar transform -> g_s (fp32).
__global__ void k_agg_last(const unsigned int* __restrict__ gin,
                           const float* __restrict__ b,
                           const float* __restrict__ Wout, int n) {
    int gt = blockIdx.x * blockDim.x + threadIdx.x;
    int u = gt >> 4, p = gt & 15;
    if (u >= n) return;
    float dinv = g_dinv[u];
    float2 acc = gather16(gin, u, p);
    float2 bb = ((const float2*)b)[p];
    float2 w = ((const float2*)Wout)[p];
    float val = fmaxf(fmaf(dinv, acc.x, bb.x), 0.f) * w.x
              + fmaxf(fmaf(dinv, acc.y, bb.y), 0.f) * w.y;
    #pragma unroll
    for (int o = 1; o < 16; o <<= 1) val += __shfl_xor_sync(FULLMASK, val, o, 16);
    if (p == 0) g_s[u] = dinv * val;
}

// Final width-1 aggregation + bias + sigmoid. Warp per node, lane-parallel.
__global__ void k_agg_out(const float* __restrict__ bout,
                          float* __restrict__ out, int n) {
    int gt = blockIdx.x * blockDim.x + threadIdx.x;
    int u = gt >> 5, lane = gt & 31;
    if (u >= n) return;
    int s0 = g_off[u], s1 = g_off[u + 1];
    float acc = 0.f;
    for (int e = s0 + lane; e < s1; e += 32) acc += g_s[__ldg(&g_csr[e])];
    #pragma unroll
    for (int o = 16; o; o >>= 1) acc += __shfl_xor_sync(FULLMASK, acc, o);
    if (lane == 0) {
        float v = fmaf(g_dinv[u], acc + g_s[u], bout[0]);
        out[u] = 1.f / (1.f + expf(-v));
    }
}

// ---------------- launch ----------------

extern "C" void kernel_launch(void* const* d_in, const int* in_sizes, int n_in,
                              void* d_out, int out_size) {
    const float* x    = (const float*)d_in[0];
    const int*   ei   = (const int*)  d_in[1];
    const float* Win  = (const float*)d_in[2];
    const float* bin  = (const float*)d_in[3];
    const float* Wmid = (const float*)d_in[4];
    const float* bmid = (const float*)d_in[5];
    const float* Wout = (const float*)d_in[6];
    const float* bout = (const float*)d_in[7];
    float* out = (float*)d_out;

    int n = in_sizes[0];
    int E = in_sizes[1] / 2;
    if (n > N_MAX) n = N_MAX;
    if (E > E_MAX) E = E_MAX;

    void *pA = nullptr, *pB = nullptr, *pDeg = nullptr, *pCur = nullptr;
    cudaGetSymbolAddress(&pA, g_A);
    cudaGetSymbolAddress(&pB, g_B);
    cudaGetSymbolAddress(&pDeg, g_deg);
    cudaGetSymbolAddress(&pCur, g_cur);
    unsigned int* A = (unsigned int*)pA;
    unsigned int* B = (unsigned int*)pB;

    const int T = 256;
    int gE   = (E + T - 1) / T;
    int gp   = (n * 16 + T - 1) / T;     // 16 threads per node
    int gw   = (n * 32 + T - 1) / T;     // warp per node (final layer)
    int nbScan = (n + 511) / 512;

    cudaMemsetAsync(pDeg, 0, n * sizeof(int), 0);
    cudaMemsetAsync(pCur, 0, n * sizeof(int), 0);

    k_count<<<gE, T>>>(ei, E);
    k_scanA<<<nbScan, 512>>>(n);
    k_scanB<<<1, 512>>>(nbScan);
    k_scanC<<<nbScan, 512>>>(n, E);
    k_fill <<<gE, T>>>(ei, E);

    k_l1      <<<gp, T>>>(x, Win, A, n);
    k_agg_mid <<<gp, T>>>(A, bin,  Wmid, B, n);   // layer 1 agg + layer 2 transform
    k_agg_mid <<<gp, T>>>(B, bmid, Wmid, A, n);   // layer 2 agg + layer 3 transform
    k_agg_last<<<gp, T>>>(A, bmid, Wout, n);      // layer 3 agg + layer 4 transform
    k_agg_out <<<gw, T>>>(bout, out, n);          // layer 4 agg + sigmoid
}